// round 11
// baseline (speedup 1.0000x reference)
#include <cuda_runtime.h>
#include <cuda_bf16.h>
#include <cuda_fp16.h>
#include <cstdint>

#define H     4096
#define NIN   700
#define T     1000
#define NOUT  20
#define NG    1024           // u32 groups of 4 neurons
#define GRPB  32             // groups per hidden block

#define GEMM_M 1024
#define GEMM_K 704
#define NBLK   33            // block 0 = readout, 1..32 = hidden
#define NTHR   128

// ---------------- device-global scratch ----------------
__device__ unsigned    g_v1T4[(size_t)(H + 1) * NG]; // packed v1T: [k][g] 4x int8; row 4096 = 0
__device__ signed char g_As8[GEMM_M * GEMM_K];
__device__ signed char g_Bs8[(size_t)H * GEMM_K];
__device__ int         g_inall[T * H];
__device__ int         g_w2Tp[(H + 1) * NOUT];       // w2T padded: row 4096 = 0
__device__ int         g_mask[6][H / 32];            // 6-slot ring of spike bitmasks
__device__ unsigned    g_bar_arrive;
__device__ unsigned    g_bar_gen;
__device__ int         g_dt[4];
__device__ int         g_bad;

// dtype codes: 0:f32 1:i32 2:i64 3:f64 4:bf16 5:f16
__device__ __forceinline__ int ldin(const void* p, long idx, int dt) {
    switch (dt) {
        case 0:  return (int)((const float*)p)[idx];
        case 1:  return ((const int*)p)[idx];
        case 2:  return (int)((const long long*)p)[idx];
        case 3:  return (int)((const double*)p)[idx];
        case 4:  return (int)__bfloat162float(((const __nv_bfloat16*)p)[idx]);
        default: return (int)__half2float(((const __half*)p)[idx]);
    }
}

__device__ __forceinline__ bool bf16ok(unsigned short h) {
    unsigned short a = h & 0x7FFF;
    return h == 0 || a == 0x3F80 || a == 0x4000 || a == 0x4040 || a == 0x4080 ||
           a == 0x40A0 || a == 0x40C0 || a == 0x40E0 || a == 0x4100;
}
__device__ __forceinline__ bool f16ok(unsigned short h) {
    unsigned short a = h & 0x7FFF;
    return h == 0 || a == 0x3C00 || a == 0x4000 || a == 0x4200 || a == 0x4400 ||
           a == 0x4500 || a == 0x4600 || a == 0x4700 || a == 0x4800;
}

__device__ int classify(const void* ptr) {
    const unsigned* p = (const unsigned*)ptr;
    const unsigned short* ph = (const unsigned short*)ptr;
    bool i64 = true;
    for (int i = 0; i < 32; i++) {
        int lo = (int)p[2 * i], hi = (int)p[2 * i + 1];
        bool sext = (hi == 0 && lo >= 0) || (hi == -1 && lo < 0);
        if (!(sext && lo >= -16 && lo <= 16)) { i64 = false; break; }
    }
    if (i64) return 2;
    bool f64 = true;
    for (int i = 0; i < 32; i++) {
        unsigned lo = p[2 * i], hi = p[2 * i + 1];
        unsigned ex = (hi >> 20) & 0x7FF;
        bool zero = (lo == 0 && (hi & 0x7FFFFFFFu) == 0);
        if (!(zero || (ex >= 1020 && ex <= 1026))) { f64 = false; break; }
    }
    if (f64) return 3;
    bool i32 = true;
    for (int i = 0; i < 64; i++) {
        int v = (int)p[i];
        if (v < -16 || v > 16) { i32 = false; break; }
    }
    if (i32) return 1;
    bool f32 = true;
    for (int i = 0; i < 64; i++)
        if (!(ph[2 * i] == 0 && bf16ok(ph[2 * i + 1]))) { f32 = false; break; }
    if (f32) return 0;
    bool b16 = true, anyEven = false;
    for (int i = 0; i < 128; i++) {
        if (!bf16ok(ph[i])) { b16 = false; break; }
        if ((i & 1) == 0 && ph[i] != 0) anyEven = true;
    }
    if (b16 && anyEven) return 4;
    bool h16 = true;
    for (int i = 0; i < 128; i++) if (!f16ok(ph[i])) { h16 = false; break; }
    if (h16) return 5;
    return 0;
}

__global__ void k_detect(const void* spk, const void* w1, const void* v1, const void* w2) {
    g_bad = 0;
    g_dt[0] = classify(spk);
    g_dt[1] = classify(w1);
    g_dt[2] = classify(v1);
    g_dt[3] = classify(w2);
}

__global__ void k_zero_out(float* out) {
    int i = blockIdx.x * blockDim.x + threadIdx.x;
    if (i < NOUT * T) out[i] = 0.0f;
}

// ---------------- conversion kernels ----------------
// v1 [h][k] -> g_v1T4[k][g] packed 4x int8 (byte i = v1[4g+i][k]); tile transpose
__global__ void k_v1T4(const void* v1) {
    __shared__ unsigned tile[32][33];
    const int dt = g_dt[2];
    int k0 = blockIdx.x * 32, g0 = blockIdx.y * 32;
    int tx = threadIdx.x, ty = threadIdx.y;
    for (int r = ty; r < 32; r += 8) {
        int gg = g0 + r;
        unsigned w = 0;
#pragma unroll
        for (int i = 0; i < 4; i++) {
            int v = ldin(v1, (long)(4 * gg + i) * H + (k0 + tx), dt);
            w |= ((unsigned)v & 0xFFu) << (8 * i);
        }
        tile[tx][r] = w;
    }
    __syncthreads();
    for (int r = ty; r < 32; r += 8)
        g_v1T4[(size_t)(k0 + r) * NG + (g0 + tx)] = tile[r][tx];
}

// zero pad rows (k = 4096)
__global__ void k_pad() {
    int i = blockIdx.x * blockDim.x + threadIdx.x;
    if (i < NG) g_v1T4[(size_t)H * NG + i] = 0u;
    if (i < NOUT) g_w2Tp[H * NOUT + i] = 0;
}

__global__ void k_packA(const void* spk) {
    int idx = blockIdx.x * blockDim.x + threadIdx.x;
    if (idx >= GEMM_M * GEMM_K) return;
    int t = idx / GEMM_K, i = idx % GEMM_K;
    int v = (t < T && i < NIN) ? ldin(spk, (long)t * NIN + i, g_dt[0]) : 0;
    g_As8[idx] = (signed char)v;
}

__global__ void k_packB(const void* w1) {
    int idx = blockIdx.x * blockDim.x + threadIdx.x;
    if (idx >= H * GEMM_K) return;
    int h = idx / GEMM_K, i = idx % GEMM_K;
    int v = (i < NIN) ? ldin(w1, (long)h * NIN + i, g_dt[1]) : 0;
    g_Bs8[idx] = (signed char)v;
}

__global__ void k_w2Tp(const void* w2) {
    int idx = blockIdx.x * blockDim.x + threadIdx.x;
    if (idx >= NOUT * H) return;
    int o = idx / H, k = idx % H;
    g_w2Tp[k * NOUT + o] = ldin(w2, (long)o * H + k, g_dt[3]);
}

// ---------------- int8 tensor-core GEMM (feed-forward currents) ----------------
__global__ void __launch_bounds__(256) k_gemm() {
    __shared__ signed char sA[64][32];
    __shared__ signed char sB[128][32];
    const int tid = threadIdx.x, lane = tid & 31, wid = tid >> 5;
    const int wm = wid & 1, wn = wid >> 1;
    const int mBase = blockIdx.y * 64, nBase = blockIdx.x * 128;

    int acc[2][4][4];
#pragma unroll
    for (int a = 0; a < 2; a++)
#pragma unroll
        for (int b = 0; b < 4; b++)
#pragma unroll
            for (int c = 0; c < 4; c++) acc[a][b][c] = 0;

    for (int k0 = 0; k0 < GEMM_K; k0 += 32) {
#pragma unroll
        for (int u = 0; u < 2; u++) {
            int w = tid + u * 256;
            int r = w >> 3, c = (w & 7) * 4;
            *(int*)&sA[r][c] = *(const int*)&g_As8[(mBase + r) * GEMM_K + k0 + c];
        }
#pragma unroll
        for (int u = 0; u < 4; u++) {
            int w = tid + u * 256;
            int r = w >> 3, c = (w & 7) * 4;
            *(int*)&sB[r][c] = *(const int*)&g_Bs8[(size_t)(nBase + r) * GEMM_K + k0 + c];
        }
        __syncthreads();

        int afrag[2][4];
#pragma unroll
        for (int mf = 0; mf < 2; mf++) {
            int r = wm * 32 + mf * 16 + (lane >> 2);
            int c = (lane & 3) * 4;
            afrag[mf][0] = *(const int*)&sA[r][c];
            afrag[mf][1] = *(const int*)&sA[r + 8][c];
            afrag[mf][2] = *(const int*)&sA[r][c + 16];
            afrag[mf][3] = *(const int*)&sA[r + 8][c + 16];
        }
        int bfrag[4][2];
#pragma unroll
        for (int nf = 0; nf < 4; nf++) {
            int col = wn * 32 + nf * 8 + (lane >> 2);
            int c = (lane & 3) * 4;
            bfrag[nf][0] = *(const int*)&sB[col][c];
            bfrag[nf][1] = *(const int*)&sB[col][c + 16];
        }
#pragma unroll
        for (int mf = 0; mf < 2; mf++)
#pragma unroll
            for (int nf = 0; nf < 4; nf++) {
                asm volatile(
                    "mma.sync.aligned.m16n8k32.row.col.s32.s8.s8.s32 "
                    "{%0,%1,%2,%3}, {%4,%5,%6,%7}, {%8,%9}, {%0,%1,%2,%3};"
                    : "+r"(acc[mf][nf][0]), "+r"(acc[mf][nf][1]),
                      "+r"(acc[mf][nf][2]), "+r"(acc[mf][nf][3])
                    : "r"(afrag[mf][0]), "r"(afrag[mf][1]),
                      "r"(afrag[mf][2]), "r"(afrag[mf][3]),
                      "r"(bfrag[nf][0]), "r"(bfrag[nf][1]));
            }
        __syncthreads();
    }
#pragma unroll
    for (int mf = 0; mf < 2; mf++) {
        int r0 = mBase + wm * 32 + mf * 16 + (lane >> 2);
#pragma unroll
        for (int nf = 0; nf < 4; nf++) {
            int c0 = nBase + wn * 32 + nf * 8 + (lane & 3) * 2;
            if (r0 < T) {
                g_inall[r0 * H + c0]     = acc[mf][nf][0];
                g_inall[r0 * H + c0 + 1] = acc[mf][nf][1];
            }
            if (r0 + 8 < T) {
                g_inall[(r0 + 8) * H + c0]     = acc[mf][nf][2];
                g_inall[(r0 + 8) * H + c0 + 1] = acc[mf][nf][3];
            }
        }
    }
}

__global__ void k_gemm_check() {
    int idx = blockIdx.x * blockDim.x + threadIdx.x;
    int t = (idx * 61) % T;
    int h = (idx * 97) % H;
    int acc = 0;
    for (int j = 0; j < GEMM_K / 4; j++)
        acc = __dp4a(*(const int*)&g_As8[t * GEMM_K + 4 * j],
                     *(const int*)&g_Bs8[(size_t)h * GEMM_K + 4 * j], acc);
    if (acc != g_inall[t * H + h]) g_bad = 1;
}

// Fallback (grid-stride; near-free when g_bad == 0).
__global__ void k_gemm_fix() {
    if (g_bad == 0) return;
    for (int idx = blockIdx.x * blockDim.x + threadIdx.x; idx < T * H;
         idx += gridDim.x * blockDim.x) {
        int t = idx / H, h = idx % H;
        int acc = 0;
        for (int j = 0; j < GEMM_K / 4; j++)
            acc = __dp4a(*(const int*)&g_As8[t * GEMM_K + 4 * j],
                         *(const int*)&g_Bs8[(size_t)h * GEMM_K + 4 * j], acc);
        g_inall[idx] = acc;
    }
}

// ---------------- memory-order helpers ----------------
__device__ __forceinline__ unsigned atomAddAcqRel(unsigned* p, unsigned v) {
    unsigned old;
    asm volatile("atom.acq_rel.gpu.add.u32 %0, [%1], %2;" : "=r"(old) : "l"(p), "r"(v) : "memory");
    return old;
}
__device__ __forceinline__ unsigned ldAcqU(unsigned* p) {
    unsigned v;
    asm volatile("ld.acquire.gpu.u32 %0, [%1];" : "=r"(v) : "l"(p) : "memory");
    return v;
}
__device__ __forceinline__ int ldAcqI(const int* p) {
    int v;
    asm volatile("ld.acquire.gpu.s32 %0, [%1];" : "=r"(v) : "l"(p) : "memory");
    return v;
}
__device__ __forceinline__ void stRel(unsigned* p, unsigned v) {
    asm volatile("st.release.gpu.u32 [%0], %1;" :: "l"(p), "r"(v) : "memory");
}
__device__ __forceinline__ void gridBarrier(unsigned& myGen) {
    __syncthreads();
    if (threadIdx.x == 0) {
        myGen++;
        unsigned a = atomAddAcqRel(&g_bar_arrive, 1u);
        if (a == NBLK - 1) {
            stRel(&g_bar_arrive, 0u);
            atomAddAcqRel(&g_bar_gen, 1u);
        } else {
            while (ldAcqU(&g_bar_gen) != myGen) { __nanosleep(32); }
        }
    }
    __syncthreads();
}

// warp-collective: scan popcounts of 128 mask words -> exclusive bases + total
__device__ __forceinline__ void scan128(const int* m, int* b, int lane) {
    int c0 = __popc(m[4 * lane + 0]);
    int c1 = __popc(m[4 * lane + 1]);
    int c2 = __popc(m[4 * lane + 2]);
    int c3 = __popc(m[4 * lane + 3]);
    int s = c0 + c1 + c2 + c3;
    int incl = s;
#pragma unroll
    for (int d = 1; d < 32; d <<= 1) {
        int v = __shfl_up_sync(0xffffffffu, incl, d);
        if (lane >= d) incl += v;
    }
    int excl = incl - s;
    b[4 * lane + 0] = excl;
    b[4 * lane + 1] = excl + c0;
    b[4 * lane + 2] = excl + c0 + c1;
    b[4 * lane + 3] = excl + c0 + c1 + c2;
    if (lane == 31) b[128] = incl;
}

__device__ __forceinline__ void buildList16(const int* m, const int* b,
                                            unsigned short* list, int w) {
    unsigned mk = (unsigned)m[w];
    int p = b[w];
    int base = w << 5;
    while (mk) {
        int bit = __ffs(mk) - 1;
        list[p++] = (unsigned short)(base + bit);
        mk &= mk - 1;
    }
}

// ---------------- persistent loop: 3 steps/phase, k-split 4 ways, 33 blocks ----------------
// Phase p (steps tb..tb+2, tb=3p): reads S_{tb-3..tb-1}, gathers fb_{tb-2..tb}
// (each warp = 1/4 of the spike list), advances LIF 3 steps (warp 0),
// publishes o_{tb..tb+2}, readout block emits rmem_{tb-2..tb}.
__global__ void __launch_bounds__(NTHR, 1) k_snn(float* __restrict__ rout) {
    __shared__ unsigned short sL[3][H];       // 24 KB
    __shared__ int sM[3][128];
    __shared__ int sB[3][129];
    __shared__ int sAcc[4][GRPB][12];         // 6 KB: [split][group][stream*4+neuron]
    __shared__ int sPart[3][NOUT][6];
    const int tid = threadIdx.x;
    const int cta = blockIdx.x;
    const int lane = tid & 31, wid = tid >> 5;
    const int g = (cta - 1) * GRPB + lane;    // hidden group (cta>=1, warp-0 lane owns it)

    int memv[4] = {0, 0, 0, 0}, synv[4] = {0, 0, 0, 0};
    int oP2 = 0, oP1 = 0;
    int rsyn = 0, rmem = 0;

    unsigned myGen = 0;
    if (tid == 0) myGen = ldAcqU(&g_bar_gen);
    for (int w = tid; w < 6 * 128; w += NTHR) ((int*)g_mask)[w] = 0;   // benign same-value
    __threadfence();
    gridBarrier(myGen);

    for (int p = 0; p < 334; p++) {
        const int tb = 3 * p;
        // ---- 1) read 3 masks ----
#pragma unroll
        for (int s = 0; s < 3; s++)
            sM[s][tid] = ldAcqI(&g_mask[(tb + 3 + s) % 6][tid]);
        __syncthreads();
        // ---- 2) scan (3 warps) ----
        if (wid < 3) scan128(sM[wid], sB[wid], lane);
        __syncthreads();
        const int K0 = sB[0][128], K1 = sB[1][128], K2 = sB[2][128];
        int Km = K0 > K1 ? K0 : K1; if (K2 > Km) Km = K2;
        const int Kpad = (Km + 3) & ~3;
        // ---- 3) build + pad lists ----
#pragma unroll
        for (int s = 0; s < 3; s++) {
            buildList16(sM[s], sB[s], sL[s], tid);
            for (int j = sB[s][128] + tid; j < Kpad; j += NTHR)
                sL[s][j] = (unsigned short)H;           // zero row
        }
        __syncthreads();

        if (cta > 0) {
            // ---- 4) k-split gather: warp `wid` takes every 4th list entry ----
            int acc[12];
#pragma unroll
            for (int i = 0; i < 12; i++) acc[i] = 0;
#pragma unroll 2
            for (int j = wid; j < Kpad; j += 4) {
                unsigned w0 = __ldg(&g_v1T4[(size_t)sL[0][j] * NG + g]);
                unsigned w1 = __ldg(&g_v1T4[(size_t)sL[1][j] * NG + g]);
                unsigned w2 = __ldg(&g_v1T4[(size_t)sL[2][j] * NG + g]);
                acc[0]  = __dp4a((int)w0, 1, acc[0]);
                acc[1]  = __dp4a((int)w0, 0x100, acc[1]);
                acc[2]  = __dp4a((int)w0, 0x10000, acc[2]);
                acc[3]  = __dp4a((int)w0, 0x1000000, acc[3]);
                acc[4]  = __dp4a((int)w1, 1, acc[4]);
                acc[5]  = __dp4a((int)w1, 0x100, acc[5]);
                acc[6]  = __dp4a((int)w1, 0x10000, acc[6]);
                acc[7]  = __dp4a((int)w1, 0x1000000, acc[7]);
                acc[8]  = __dp4a((int)w2, 1, acc[8]);
                acc[9]  = __dp4a((int)w2, 0x100, acc[9]);
                acc[10] = __dp4a((int)w2, 0x10000, acc[10]);
                acc[11] = __dp4a((int)w2, 0x1000000, acc[11]);
            }
#pragma unroll
            for (int i = 0; i < 12; i++) sAcc[wid][lane][i] = acc[i];
            __syncthreads();

            if (wid == 0) {
                // ---- 5) reduce 4 splits ----
                int a[12];
#pragma unroll
                for (int i = 0; i < 12; i++)
                    a[i] = sAcc[0][lane][i] + sAcc[1][lane][i] +
                           sAcc[2][lane][i] + sAcc[3][lane][i];
                // ---- 6) inc rows ----
                int4 incv[3];
#pragma unroll
                for (int s = 0; s < 3; s++) {
                    int tr = tb - 2 + s;
                    incv[s] = (tr >= 0) ? __ldg((const int4*)&g_inall[tr * H + 4 * g])
                                        : make_int4(0, 0, 0, 0);
                }
                const int iA[4] = {incv[0].x, incv[0].y, incv[0].z, incv[0].w};
                const int iB[4] = {incv[1].x, incv[1].y, incv[1].z, incv[1].w};
                const int iC[4] = {incv[2].x, incv[2].y, incv[2].z, incv[2].w};
                // ---- 7) LIF: 3 steps x 4 neurons ----
                int nib0 = 0, nib1 = 0, nib2 = 0;
#pragma unroll
                for (int i = 0; i < 4; i++) {
                    int m = memv[i], s = synv[i];
                    const int om2 = (oP2 >> i) & 1, om1 = (oP1 >> i) & 1;
                    s = s - (s >> 4) + iA[i] + a[i];          // syn_{tb-2}
                    int m0 = om2 ? 0 : m;
                    m = m0 - (m0 >> 3) + s;                   // mem_{tb-1}
                    s = s - (s >> 4) + iB[i] + a[4 + i];      // syn_{tb-1}
                    int m1 = om1 ? 0 : m;
                    int o0 = (m1 > 1) ? 1 : 0;                // o_{tb}
                    m = m1 - (m1 >> 3) + s;                   // mem_{tb}
                    s = s - (s >> 4) + iC[i] + a[8 + i];      // syn_{tb}
                    int m2 = o0 ? 0 : m;
                    int o1 = (m2 > 1) ? 1 : 0;                // o_{tb+1}
                    m = m2 - (m2 >> 3) + s;                   // mem_{tb+1}
                    int m3 = o1 ? 0 : m;
                    int o2 = (m3 > 1) ? 1 : 0;                // o_{tb+2}
                    memv[i] = m; synv[i] = s;
                    nib0 |= o0 << i; nib1 |= o1 << i; nib2 |= o2 << i;
                }
                oP2 = nib1; oP1 = nib2;
                // ---- 8) publish: 8-lane subgroups assemble 32-bit words ----
                const int sh = 4 * (lane & 7);
                int v0 = nib0 << sh, v1 = nib1 << sh, v2 = nib2 << sh;
#pragma unroll
                for (int d = 1; d < 8; d <<= 1) {
                    v0 |= __shfl_xor_sync(0xffffffffu, v0, d);
                    v1 |= __shfl_xor_sync(0xffffffffu, v1, d);
                    v2 |= __shfl_xor_sync(0xffffffffu, v2, d);
                }
                if ((lane & 7) == 0) {
                    const int wI = g >> 3;
                    g_mask[tb % 6][wI]       = v0;
                    g_mask[(tb + 1) % 6][wI] = v1;
                    g_mask[(tb + 2) % 6][wI] = v2;
                    __threadfence();
                }
            }
        } else {
            // ---- readout block: rc_s = w2 @ S_{tb-3+s}; emit rmem_{tb-2+s} ----
            if (tid < 120) {
                const int o = tid % NOUT, q = tid / NOUT;
                int pa = 0, pb = 0, pc = 0;
                for (int j = q; j < Kpad; j += 6) {
                    pa += __ldg(&g_w2Tp[(int)sL[0][j] * NOUT + o]);
                    pb += __ldg(&g_w2Tp[(int)sL[1][j] * NOUT + o]);
                    pc += __ldg(&g_w2Tp[(int)sL[2][j] * NOUT + o]);
                }
                sPart[0][o][q] = pa; sPart[1][o][q] = pb; sPart[2][o][q] = pc;
            }
            __syncthreads();
            if (tid < NOUT) {
#pragma unroll
                for (int s = 0; s < 3; s++) {
                    int rc = sPart[s][tid][0] + sPart[s][tid][1] + sPart[s][tid][2] +
                             sPart[s][tid][3] + sPart[s][tid][4] + sPart[s][tid][5];
                    rsyn = rsyn - (rsyn >> 4) + rc;
                    rmem = rmem - (rmem >> 3) + rsyn;
                    int t = tb - 2 + s;
                    if (t >= 0) rout[tid * T + t] = (float)rmem;
                }
            }
        }
        // ---- 9) one barrier per 3 steps ----
        gridBarrier(myGen);
    }
}

// ---------------- launch ----------------
extern "C" void kernel_launch(void* const* d_in, const int* in_sizes, int n_in,
                              void* d_out, int out_size) {
    const void *spk = d_in[0], *w1 = d_in[1], *v1 = d_in[2], *w2 = d_in[3];
    for (int i = 0; i < n_in; i++) {
        long s = in_sizes[i];
        if (s == (long)T * NIN || s == 4L * T * NIN || s == 8L * T * NIN || s == 2L * T * NIN)
            spk = d_in[i];
        else if (s == (long)H * NIN || s == 4L * H * NIN || s == 8L * H * NIN || s == 2L * H * NIN)
            w1 = d_in[i];
        else if (s == (long)H * H || s == 4L * H * H || s == 8L * H * H || s == 2L * H * H)
            v1 = d_in[i];
        else if (s == (long)NOUT * H || s == 4L * NOUT * H || s == 8L * NOUT * H || s == 2L * NOUT * H)
            w2 = d_in[i];
    }
    (void)out_size;

    k_detect<<<1, 1>>>(spk, w1, v1, w2);
    k_zero_out<<<(NOUT * T + 255) / 256, 256>>>((float*)d_out);
    k_v1T4<<<dim3(H / 32, NG / 32), dim3(32, 8)>>>(v1);
    k_pad<<<(NG + 255) / 256, 256>>>();
    k_packA<<<(GEMM_M * GEMM_K + 255) / 256, 256>>>(spk);
    k_packB<<<(H * GEMM_K + 255) / 256, 256>>>(w1);
    k_w2Tp<<<(NOUT * H + 255) / 256, 256>>>(w2);
    k_gemm<<<dim3(H / 128, GEMM_M / 64), 256>>>();
    k_gemm_check<<<16, 256>>>();
    k_gemm_fix<<<256, 256>>>();
    k_snn<<<NBLK, NTHR>>>((float*)d_out);
}

// round 13
// speedup vs baseline: 1.0758x; 1.0758x over previous
#include <cuda_runtime.h>
#include <cuda_bf16.h>
#include <cuda_fp16.h>
#include <cstdint>

#define H     4096
#define NIN   700
#define T     1000
#define NOUT  20
#define NG    1024           // u32 groups of 4 neurons
#define GRPB  32             // groups per hidden block

#define GEMM_M 1024
#define GEMM_K 704
#define NBLK   33            // block 0 = readout, 1..32 = hidden
#define NTHR   128
#define NHID   32            // hidden blocks
#define RING   12            // mask ring depth (steps)

// ---------------- device-global scratch ----------------
__device__ unsigned           g_v1T4[(size_t)(H + 1) * NG]; // packed v1T: [k][g]; row 4096 = 0
__device__ signed char        g_As8[GEMM_M * GEMM_K];
__device__ signed char        g_Bs8[(size_t)H * GEMM_K];
__device__ int                g_inall[T * H];
__device__ int                g_w2Tp[(H + 1) * NOUT];
__device__ unsigned long long g_maskT[RING][H / 32];        // (tag<<32)|mask, tag = step+16
__device__ int                g_rc[T * NOUT];               // per-step readout currents
__device__ int                g_rcnt[T];                    // #hidden blocks done per step
__device__ unsigned           g_bar_arrive;                 // startup barrier
__device__ unsigned           g_bar_gen;
__device__ int                g_dt[4];
__device__ int                g_bad;

// dtype codes: 0:f32 1:i32 2:i64 3:f64 4:bf16 5:f16
__device__ __forceinline__ int ldin(const void* p, long idx, int dt) {
    switch (dt) {
        case 0:  return (int)((const float*)p)[idx];
        case 1:  return ((const int*)p)[idx];
        case 2:  return (int)((const long long*)p)[idx];
        case 3:  return (int)((const double*)p)[idx];
        case 4:  return (int)__bfloat162float(((const __nv_bfloat16*)p)[idx]);
        default: return (int)__half2float(((const __half*)p)[idx]);
    }
}

__device__ __forceinline__ bool bf16ok(unsigned short h) {
    unsigned short a = h & 0x7FFF;
    return h == 0 || a == 0x3F80 || a == 0x4000 || a == 0x4040 || a == 0x4080 ||
           a == 0x40A0 || a == 0x40C0 || a == 0x40E0 || a == 0x4100;
}
__device__ __forceinline__ bool f16ok(unsigned short h) {
    unsigned short a = h & 0x7FFF;
    return h == 0 || a == 0x3C00 || a == 0x4000 || a == 0x4200 || a == 0x4400 ||
           a == 0x4500 || a == 0x4600 || a == 0x4700 || a == 0x4800;
}

__device__ int classify(const void* ptr) {
    const unsigned* p = (const unsigned*)ptr;
    const unsigned short* ph = (const unsigned short*)ptr;
    bool i64 = true;
    for (int i = 0; i < 32; i++) {
        int lo = (int)p[2 * i], hi = (int)p[2 * i + 1];
        bool sext = (hi == 0 && lo >= 0) || (hi == -1 && lo < 0);
        if (!(sext && lo >= -16 && lo <= 16)) { i64 = false; break; }
    }
    if (i64) return 2;
    bool f64 = true;
    for (int i = 0; i < 32; i++) {
        unsigned lo = p[2 * i], hi = p[2 * i + 1];
        unsigned ex = (hi >> 20) & 0x7FF;
        bool zero = (lo == 0 && (hi & 0x7FFFFFFFu) == 0);
        if (!(zero || (ex >= 1020 && ex <= 1026))) { f64 = false; break; }
    }
    if (f64) return 3;
    bool i32 = true;
    for (int i = 0; i < 64; i++) {
        int v = (int)p[i];
        if (v < -16 || v > 16) { i32 = false; break; }
    }
    if (i32) return 1;
    bool f32 = true;
    for (int i = 0; i < 64; i++)
        if (!(ph[2 * i] == 0 && bf16ok(ph[2 * i + 1]))) { f32 = false; break; }
    if (f32) return 0;
    bool b16 = true, anyEven = false;
    for (int i = 0; i < 128; i++) {
        if (!bf16ok(ph[i])) { b16 = false; break; }
        if ((i & 1) == 0 && ph[i] != 0) anyEven = true;
    }
    if (b16 && anyEven) return 4;
    bool h16 = true;
    for (int i = 0; i < 128; i++) if (!f16ok(ph[i])) { h16 = false; break; }
    if (h16) return 5;
    return 0;
}

__global__ void k_detect(const void* spk, const void* w1, const void* v1, const void* w2) {
    g_bad = 0;
    g_dt[0] = classify(spk);
    g_dt[1] = classify(w1);
    g_dt[2] = classify(v1);
    g_dt[3] = classify(w2);
}

__global__ void k_zero_out(float* out) {
    int i = blockIdx.x * blockDim.x + threadIdx.x;
    if (i < NOUT * T) out[i] = 0.0f;
}

// ---------------- conversion kernels ----------------
__global__ void k_v1T4(const void* v1) {
    __shared__ unsigned tile[32][33];
    const int dt = g_dt[2];
    int k0 = blockIdx.x * 32, g0 = blockIdx.y * 32;
    int tx = threadIdx.x, ty = threadIdx.y;
    for (int r = ty; r < 32; r += 8) {
        int gg = g0 + r;
        unsigned w = 0;
#pragma unroll
        for (int i = 0; i < 4; i++) {
            int v = ldin(v1, (long)(4 * gg + i) * H + (k0 + tx), dt);
            w |= ((unsigned)v & 0xFFu) << (8 * i);
        }
        tile[tx][r] = w;
    }
    __syncthreads();
    for (int r = ty; r < 32; r += 8)
        g_v1T4[(size_t)(k0 + r) * NG + (g0 + tx)] = tile[r][tx];
}

__global__ void k_pad() {
    int i = blockIdx.x * blockDim.x + threadIdx.x;
    if (i < NG) g_v1T4[(size_t)H * NG + i] = 0u;
    if (i < NOUT) g_w2Tp[H * NOUT + i] = 0;
}

__global__ void k_packA(const void* spk) {
    int idx = blockIdx.x * blockDim.x + threadIdx.x;
    if (idx >= GEMM_M * GEMM_K) return;
    int t = idx / GEMM_K, i = idx % GEMM_K;
    int v = (t < T && i < NIN) ? ldin(spk, (long)t * NIN + i, g_dt[0]) : 0;
    g_As8[idx] = (signed char)v;
}

__global__ void k_packB(const void* w1) {
    int idx = blockIdx.x * blockDim.x + threadIdx.x;
    if (idx >= H * GEMM_K) return;
    int h = idx / GEMM_K, i = idx % GEMM_K;
    int v = (i < NIN) ? ldin(w1, (long)h * NIN + i, g_dt[1]) : 0;
    g_Bs8[idx] = (signed char)v;
}

__global__ void k_w2Tp(const void* w2) {
    int idx = blockIdx.x * blockDim.x + threadIdx.x;
    if (idx >= NOUT * H) return;
    int o = idx / H, k = idx % H;
    g_w2Tp[k * NOUT + o] = ldin(w2, (long)o * H + k, g_dt[3]);
}

// ---------------- int8 tensor-core GEMM ----------------
__global__ void __launch_bounds__(256) k_gemm() {
    __shared__ signed char sA[64][32];
    __shared__ signed char sB[128][32];
    const int tid = threadIdx.x, lane = tid & 31, wid = tid >> 5;
    const int wm = wid & 1, wn = wid >> 1;
    const int mBase = blockIdx.y * 64, nBase = blockIdx.x * 128;

    int acc[2][4][4];
#pragma unroll
    for (int a = 0; a < 2; a++)
#pragma unroll
        for (int b = 0; b < 4; b++)
#pragma unroll
            for (int c = 0; c < 4; c++) acc[a][b][c] = 0;

    for (int k0 = 0; k0 < GEMM_K; k0 += 32) {
#pragma unroll
        for (int u = 0; u < 2; u++) {
            int w = tid + u * 256;
            int r = w >> 3, c = (w & 7) * 4;
            *(int*)&sA[r][c] = *(const int*)&g_As8[(mBase + r) * GEMM_K + k0 + c];
        }
#pragma unroll
        for (int u = 0; u < 4; u++) {
            int w = tid + u * 256;
            int r = w >> 3, c = (w & 7) * 4;
            *(int*)&sB[r][c] = *(const int*)&g_Bs8[(size_t)(nBase + r) * GEMM_K + k0 + c];
        }
        __syncthreads();

        int afrag[2][4];
#pragma unroll
        for (int mf = 0; mf < 2; mf++) {
            int r = wm * 32 + mf * 16 + (lane >> 2);
            int c = (lane & 3) * 4;
            afrag[mf][0] = *(const int*)&sA[r][c];
            afrag[mf][1] = *(const int*)&sA[r + 8][c];
            afrag[mf][2] = *(const int*)&sA[r][c + 16];
            afrag[mf][3] = *(const int*)&sA[r + 8][c + 16];
        }
        int bfrag[4][2];
#pragma unroll
        for (int nf = 0; nf < 4; nf++) {
            int col = wn * 32 + nf * 8 + (lane >> 2);
            int c = (lane & 3) * 4;
            bfrag[nf][0] = *(const int*)&sB[col][c];
            bfrag[nf][1] = *(const int*)&sB[col][c + 16];
        }
#pragma unroll
        for (int mf = 0; mf < 2; mf++)
#pragma unroll
            for (int nf = 0; nf < 4; nf++) {
                asm volatile(
                    "mma.sync.aligned.m16n8k32.row.col.s32.s8.s8.s32 "
                    "{%0,%1,%2,%3}, {%4,%5,%6,%7}, {%8,%9}, {%0,%1,%2,%3};"
                    : "+r"(acc[mf][nf][0]), "+r"(acc[mf][nf][1]),
                      "+r"(acc[mf][nf][2]), "+r"(acc[mf][nf][3])
                    : "r"(afrag[mf][0]), "r"(afrag[mf][1]),
                      "r"(afrag[mf][2]), "r"(afrag[mf][3]),
                      "r"(bfrag[nf][0]), "r"(bfrag[nf][1]));
            }
        __syncthreads();
    }
#pragma unroll
    for (int mf = 0; mf < 2; mf++) {
        int r0 = mBase + wm * 32 + mf * 16 + (lane >> 2);
#pragma unroll
        for (int nf = 0; nf < 4; nf++) {
            int c0 = nBase + wn * 32 + nf * 8 + (lane & 3) * 2;
            if (r0 < T) {
                g_inall[r0 * H + c0]     = acc[mf][nf][0];
                g_inall[r0 * H + c0 + 1] = acc[mf][nf][1];
            }
            if (r0 + 8 < T) {
                g_inall[(r0 + 8) * H + c0]     = acc[mf][nf][2];
                g_inall[(r0 + 8) * H + c0 + 1] = acc[mf][nf][3];
            }
        }
    }
}

__global__ void k_gemm_check() {
    int idx = blockIdx.x * blockDim.x + threadIdx.x;
    int t = (idx * 61) % T;
    int h = (idx * 97) % H;
    int acc = 0;
    for (int j = 0; j < GEMM_K / 4; j++)
        acc = __dp4a(*(const int*)&g_As8[t * GEMM_K + 4 * j],
                     *(const int*)&g_Bs8[(size_t)h * GEMM_K + 4 * j], acc);
    if (acc != g_inall[t * H + h]) g_bad = 1;
}

__global__ void k_gemm_fix() {
    if (g_bad == 0) return;
    for (int idx = blockIdx.x * blockDim.x + threadIdx.x; idx < T * H;
         idx += gridDim.x * blockDim.x) {
        int t = idx / H, h = idx % H;
        int acc = 0;
        for (int j = 0; j < GEMM_K / 4; j++)
            acc = __dp4a(*(const int*)&g_As8[t * GEMM_K + 4 * j],
                         *(const int*)&g_Bs8[(size_t)h * GEMM_K + 4 * j], acc);
        g_inall[idx] = acc;
    }
}

// ---------------- memory-order helpers ----------------
__device__ __forceinline__ unsigned atomAddAcqRel(unsigned* p, unsigned v) {
    unsigned old;
    asm volatile("atom.acq_rel.gpu.add.u32 %0, [%1], %2;" : "=r"(old) : "l"(p), "r"(v) : "memory");
    return old;
}
__device__ __forceinline__ unsigned ldAcqU(unsigned* p) {
    unsigned v;
    asm volatile("ld.acquire.gpu.u32 %0, [%1];" : "=r"(v) : "l"(p) : "memory");
    return v;
}
__device__ __forceinline__ int ldAcqI(const int* p) {
    int v;
    asm volatile("ld.acquire.gpu.s32 %0, [%1];" : "=r"(v) : "l"(p) : "memory");
    return v;
}
__device__ __forceinline__ unsigned long long ldAcq64(const unsigned long long* p) {
    unsigned long long v;
    asm volatile("ld.acquire.gpu.u64 %0, [%1];" : "=l"(v) : "l"(p) : "memory");
    return v;
}
__device__ __forceinline__ void stRel64(unsigned long long* p, unsigned long long v) {
    asm volatile("st.release.gpu.u64 [%0], %1;" :: "l"(p), "l"(v) : "memory");
}
__device__ __forceinline__ void stRel(unsigned* p, unsigned v) {
    asm volatile("st.release.gpu.u32 [%0], %1;" :: "l"(p), "r"(v) : "memory");
}
// Poll a tagged mask word with bounded backoff (fast spin first, then sleep).
__device__ __forceinline__ unsigned pollTag(const unsigned long long* p, unsigned tag) {
    unsigned long long w = ldAcq64(p);
    if ((unsigned)(w >> 32) == tag) return (unsigned)w;
    int spins = 0;
    for (;;) {
        w = ldAcq64(p);
        if ((unsigned)(w >> 32) == tag) return (unsigned)w;
        if (++spins > 32) __nanosleep(32);
    }
}
// startup-only grid barrier
__device__ __forceinline__ void startBarrier(unsigned& myGen) {
    __syncthreads();
    if (threadIdx.x == 0) {
        myGen++;
        unsigned a = atomAddAcqRel(&g_bar_arrive, 1u);
        if (a == NBLK - 1) {
            stRel(&g_bar_arrive, 0u);
            atomAddAcqRel(&g_bar_gen, 1u);
        } else {
            int spins = 0;
            while (ldAcqU(&g_bar_gen) != myGen) { if (++spins > 32) __nanosleep(64); }
        }
    }
    __syncthreads();
}

__device__ __forceinline__ void scan128(const int* m, int* b, int lane) {
    int c0 = __popc(m[4 * lane + 0]);
    int c1 = __popc(m[4 * lane + 1]);
    int c2 = __popc(m[4 * lane + 2]);
    int c3 = __popc(m[4 * lane + 3]);
    int s = c0 + c1 + c2 + c3;
    int incl = s;
#pragma unroll
    for (int d = 1; d < 32; d <<= 1) {
        int v = __shfl_up_sync(0xffffffffu, incl, d);
        if (lane >= d) incl += v;
    }
    int excl = incl - s;
    b[4 * lane + 0] = excl;
    b[4 * lane + 1] = excl + c0;
    b[4 * lane + 2] = excl + c0 + c1;
    b[4 * lane + 3] = excl + c0 + c1 + c2;
    if (lane == 31) b[128] = incl;
}

__device__ __forceinline__ void buildList16(const int* m, const int* b,
                                            unsigned short* list, int w) {
    unsigned mk = (unsigned)m[w];
    int p = b[w];
    int base = w << 5;
    while (mk) {
        int bit = __ffs(mk) - 1;
        list[p++] = (unsigned short)(base + bit);
        mk &= mk - 1;
    }
}

// ---------------- persistent loop: NO grid barrier — tagged dataflow masks ----------------
// Mask word for step t: (u64)(t+16)<<32 | mask32, release-stored; consumers
// acquire-spin until the tag matches. Ring depth 12 steps; the dependency chain
// bounds inter-block skew so overwrite-before-read is impossible (proof: a block
// entering phase P has observed all publishes of phase P-1, hence all reads of
// phase P-1 are done; phase P overwrites only step 3P-12, read in phase P-3).
__global__ void __launch_bounds__(NTHR, 1) k_snn(float* __restrict__ rout) {
    __shared__ unsigned short sL[3][H];       // 24 KB
    __shared__ int sM[3][128];
    __shared__ int sB[3][129];
    __shared__ int sAcc[4][GRPB][12];
    __shared__ unsigned short sSpk[3][GRPB * 4];
    __shared__ int sCnt[3];
    const int tid = threadIdx.x;
    const int cta = blockIdx.x;
    const int lane = tid & 31, wid = tid >> 5;
    const int g = (cta - 1) * GRPB + lane;    // hidden group (warp-0 lane owns it)

    // ---- init (cta 0 zeroes rc/rcnt and preseeds ring) ----
    unsigned myGen = 0;
    if (tid == 0) myGen = ldAcqU(&g_bar_gen);
    if (cta == 0) {
        for (int i = tid; i < T; i += NTHR) g_rcnt[i] = 0;
        for (int i = tid; i < T * NOUT; i += NTHR) g_rc[i] = 0;
        // preseed steps -3,-2,-1 (slots 9,10,11) with tags 13,14,15, empty masks
        if (tid < 128) {
#pragma unroll
            for (int s = 0; s < 3; s++)
                g_maskT[9 + s][tid] = ((unsigned long long)(13 + s)) << 32;
        }
        __threadfence();
    }
    startBarrier(myGen);

    // ---- readout block: consumes g_rc / g_rcnt only ----
    if (cta == 0) {
        if (wid == 0) {
            int rsyn = 0, rmem = 0;
            for (int t = 0; t < T; t++) {
                int rc = 0;
                if (t > 0) {
                    if (lane == 0) {
                        int spins = 0;
                        while (ldAcqI(&g_rcnt[t - 1]) != NHID) {
                            if (++spins > 32) __nanosleep(64);
                        }
                    }
                    __syncwarp();
                    if (lane < NOUT) rc = g_rc[(t - 1) * NOUT + lane];
                }
                if (lane < NOUT) {
                    rsyn = rsyn - (rsyn >> 4) + rc;
                    rmem = rmem - (rmem >> 3) + rsyn;
                    rout[lane * T + t] = (float)rmem;
                }
            }
        }
        return;
    }

    // ---- hidden blocks ----
    int memv[4] = {0, 0, 0, 0}, synv[4] = {0, 0, 0, 0};
    int oP2 = 0, oP1 = 0;

    for (int p = 0; p < 334; p++) {
        const int tb = 3 * p;
        // 1) poll 3 tagged mask rows (steps tb-3, tb-2, tb-1)
        {
            const int t0 = tb - 3;
            const unsigned e0 = (unsigned)(t0 + 16);
            sM[0][tid] = (int)pollTag(&g_maskT[(t0 + RING) % RING][tid], e0);
            sM[1][tid] = (int)pollTag(&g_maskT[(t0 + 1 + RING) % RING][tid], e0 + 1);
            sM[2][tid] = (int)pollTag(&g_maskT[(t0 + 2 + RING) % RING][tid], e0 + 2);
        }
        __syncthreads();
        // 2) scan
        if (wid < 3) scan128(sM[wid], sB[wid], lane);
        __syncthreads();
        const int K0 = sB[0][128], K1 = sB[1][128], K2 = sB[2][128];
        int Km = K0 > K1 ? K0 : K1; if (K2 > Km) Km = K2;
        const int Kpad = (Km + 3) & ~3;
        // 3) build + pad lists
#pragma unroll
        for (int s = 0; s < 3; s++) {
            buildList16(sM[s], sB[s], sL[s], tid);
            for (int j = sB[s][128] + tid; j < Kpad; j += NTHR)
                sL[s][j] = (unsigned short)H;
        }
        __syncthreads();
        // 4) k-split gather (each warp every 4th entry)
        int acc[12];
#pragma unroll
        for (int i = 0; i < 12; i++) acc[i] = 0;
#pragma unroll 2
        for (int j = wid; j < Kpad; j += 4) {
            unsigned w0 = __ldg(&g_v1T4[(size_t)sL[0][j] * NG + g]);
            unsigned w1 = __ldg(&g_v1T4[(size_t)sL[1][j] * NG + g]);
            unsigned w2 = __ldg(&g_v1T4[(size_t)sL[2][j] * NG + g]);
            acc[0]  = __dp4a((int)w0, 1, acc[0]);
            acc[1]  = __dp4a((int)w0, 0x100, acc[1]);
            acc[2]  = __dp4a((int)w0, 0x10000, acc[2]);
            acc[3]  = __dp4a((int)w0, 0x1000000, acc[3]);
            acc[4]  = __dp4a((int)w1, 1, acc[4]);
            acc[5]  = __dp4a((int)w1, 0x100, acc[5]);
            acc[6]  = __dp4a((int)w1, 0x10000, acc[6]);
            acc[7]  = __dp4a((int)w1, 0x1000000, acc[7]);
            acc[8]  = __dp4a((int)w2, 1, acc[8]);
            acc[9]  = __dp4a((int)w2, 0x100, acc[9]);
            acc[10] = __dp4a((int)w2, 0x10000, acc[10]);
            acc[11] = __dp4a((int)w2, 0x1000000, acc[11]);
        }
#pragma unroll
        for (int i = 0; i < 12; i++) sAcc[wid][lane][i] = acc[i];
        __syncthreads();

        if (wid == 0) {
            // 5) reduce splits
            int a[12];
#pragma unroll
            for (int i = 0; i < 12; i++)
                a[i] = sAcc[0][lane][i] + sAcc[1][lane][i] +
                       sAcc[2][lane][i] + sAcc[3][lane][i];
            // 6) inc rows
            int4 incv[3];
#pragma unroll
            for (int s = 0; s < 3; s++) {
                int tr = tb - 2 + s;
                incv[s] = (tr >= 0 && tr < T) ? __ldg((const int4*)&g_inall[tr * H + 4 * g])
                                              : make_int4(0, 0, 0, 0);
            }
            const int iA[4] = {incv[0].x, incv[0].y, incv[0].z, incv[0].w};
            const int iB[4] = {incv[1].x, incv[1].y, incv[1].z, incv[1].w};
            const int iC[4] = {incv[2].x, incv[2].y, incv[2].z, incv[2].w};
            // 7) LIF: 3 steps x 4 neurons
            int nib0 = 0, nib1 = 0, nib2 = 0;
#pragma unroll
            for (int i = 0; i < 4; i++) {
                int m = memv[i], s = synv[i];
                const int om2 = (oP2 >> i) & 1, om1 = (oP1 >> i) & 1;
                s = s - (s >> 4) + iA[i] + a[i];          // syn_{tb-2}
                int m0 = om2 ? 0 : m;
                m = m0 - (m0 >> 3) + s;                   // mem_{tb-1}
                s = s - (s >> 4) + iB[i] + a[4 + i];      // syn_{tb-1}
                int m1 = om1 ? 0 : m;
                int o0 = (m1 > 1) ? 1 : 0;                // o_{tb}
                m = m1 - (m1 >> 3) + s;                   // mem_{tb}
                s = s - (s >> 4) + iC[i] + a[8 + i];      // syn_{tb}
                int m2 = o0 ? 0 : m;
                int o1 = (m2 > 1) ? 1 : 0;                // o_{tb+1}
                m = m2 - (m2 >> 3) + s;                   // mem_{tb+1}
                int m3 = o1 ? 0 : m;
                int o2 = (m3 > 1) ? 1 : 0;                // o_{tb+2}
                memv[i] = m; synv[i] = s;
                nib0 |= o0 << i; nib1 |= o1 << i; nib2 |= o2 << i;
            }
            oP2 = nib1; oP1 = nib2;
            // 8) publish tagged mask words ASAP (consumers' critical path)
            const int sh = 4 * (lane & 7);
            int v0 = nib0 << sh, v1 = nib1 << sh, v2 = nib2 << sh;
#pragma unroll
            for (int d = 1; d < 8; d <<= 1) {
                v0 |= __shfl_xor_sync(0xffffffffu, v0, d);
                v1 |= __shfl_xor_sync(0xffffffffu, v1, d);
                v2 |= __shfl_xor_sync(0xffffffffu, v2, d);
            }
            if ((lane & 7) == 0) {
                const int wI = g >> 3;
                if (tb < T)
                    stRel64(&g_maskT[tb % RING][wI],
                            (((unsigned long long)(tb + 16)) << 32) | (unsigned)v0);
                if (tb + 1 < T)
                    stRel64(&g_maskT[(tb + 1) % RING][wI],
                            (((unsigned long long)(tb + 17)) << 32) | (unsigned)v1);
                if (tb + 2 < T)
                    stRel64(&g_maskT[(tb + 2) % RING][wI],
                            (((unsigned long long)(tb + 18)) << 32) | (unsigned)v2);
            }
            // 9) block-local spike lists for readout partials
            if (lane < 3) sCnt[lane] = 0;
            __syncwarp();
            const int nibs[3] = {nib0, nib1, nib2};
#pragma unroll
            for (int s = 0; s < 3; s++) {
                int nb = nibs[s];
                while (nb) {
                    int i = __ffs(nb) - 1;
                    nb &= nb - 1;
                    int idx = atomicAdd(&sCnt[s], 1);
                    sSpk[s][idx] = (unsigned short)(4 * g + i);
                }
            }
        }
        __syncthreads();
        // 10) readout partials (warps 1..3 -> steps tb..tb+2)
        if (wid >= 1) {
            const int s = wid - 1;
            const int t = tb + s;
            if (t < T) {
                const int cnt = sCnt[s];
                if (lane < NOUT && cnt) {
                    int rc = 0;
                    for (int j = 0; j < cnt; j++)
                        rc += __ldg(&g_w2Tp[(int)sSpk[s][j] * NOUT + lane]);
                    atomicAdd(&g_rc[t * NOUT + lane], rc);
                }
                __syncwarp();
                if (lane == 0) {
                    __threadfence();
                    atomicAdd(&g_rcnt[t], 1);
                }
            }
        }
        // no barrier — next phase's polls provide all ordering
    }
}

// ---------------- launch ----------------
extern "C" void kernel_launch(void* const* d_in, const int* in_sizes, int n_in,
                              void* d_out, int out_size) {
    const void *spk = d_in[0], *w1 = d_in[1], *v1 = d_in[2], *w2 = d_in[3];
    for (int i = 0; i < n_in; i++) {
        long s = in_sizes[i];
        if (s == (long)T * NIN || s == 4L * T * NIN || s == 8L * T * NIN || s == 2L * T * NIN)
            spk = d_in[i];
        else if (s == (long)H * NIN || s == 4L * H * NIN || s == 8L * H * NIN || s == 2L * H * NIN)
            w1 = d_in[i];
        else if (s == (long)H * H || s == 4L * H * H || s == 8L * H * H || s == 2L * H * H)
            v1 = d_in[i];
        else if (s == (long)NOUT * H || s == 4L * NOUT * H || s == 8L * NOUT * H || s == 2L * NOUT * H)
            w2 = d_in[i];
    }
    (void)out_size;

    k_detect<<<1, 1>>>(spk, w1, v1, w2);
    k_zero_out<<<(NOUT * T + 255) / 256, 256>>>((float*)d_out);
    k_v1T4<<<dim3(H / 32, NG / 32), dim3(32, 8)>>>(v1);
    k_pad<<<(NG + 255) / 256, 256>>>();
    k_packA<<<(GEMM_M * GEMM_K + 255) / 256, 256>>>(spk);
    k_packB<<<(H * GEMM_K + 255) / 256, 256>>>(w1);
    k_w2Tp<<<(NOUT * H + 255) / 256, 256>>>(w2);
    k_gemm<<<dim3(H / 128, GEMM_M / 64), 256>>>();
    k_gemm_check<<<16, 256>>>();
    k_gemm_fix<<<256, 256>>>();
    k_snn<<<NBLK, NTHR>>>((float*)d_out);
}